// round 7
// baseline (speedup 1.0000x reference)
#include <cuda_runtime.h>
#include <cstdint>

// ---------------- problem dims ----------------
#define Bb 32
#define Nn 1024
#define Cc 1024
#define Ll 16
#define Hh 512
#define BNC (Bb*Nn*Cc)       // 33554432
#define BLC (Bb*Ll*Cc)       // 524288 (== B*L*N == chain GEMM size MN)

// ---------------- packed f32x2 FMA (sm_103a FFMA2, PTX-only) ----------------
union F2U { float2 f; unsigned long long u; };
__device__ __forceinline__ float2 ffma2(float2 a, float2 b, float2 c)
{
    F2U ua, ub, uc, ud;
    ua.f = a; ub.f = b; uc.f = c;
    asm("fma.rn.f32x2 %0, %1, %2, %3;"
        : "=l"(ud.u) : "l"(ua.u), "l"(ub.u), "l"(uc.u));
    return ud.f;
}

// ---------------- scratch ----------------
__device__ float g_attn[Bb*Ll*Nn];   // softmax weights, [b][l][n]
__device__ float g_T[BLC];           // tokens [b][l][c]
__device__ float g_Tp[8*BLC];        // shared partial scratch: k1(2), k3(8), gemm split-K(8)
__device__ float g_kq[BLC];          // [token][0:512]=k, [512:1024]=q
__device__ float g_Td[BLC];          // T_dash
__device__ float g_h[BLC];           // relu(f1)
__device__ float g_TK[BLC];          // T_out @ k_W + k_b
__device__ float g_U[BLC];           // TK @ q_W^T
__device__ float g_cb[Bb*Ll];        // q_b . TK[b,l]
__device__ float g_Wkq[Cc*Cc];       // [key_W | query_W]
__device__ float g_bkq[Cc];          // [key_b | query_b]

// =================================================================
// pack key/query weights into one [1024][1024] matrix + bias
// =================================================================
__global__ __launch_bounds__(256) void k_pack_kq(
    const float* __restrict__ kW, const float* __restrict__ kb,
    const float* __restrict__ qW, const float* __restrict__ qb,
    float* __restrict__ W, float* __restrict__ bias)
{
    int idx = blockIdx.x*256 + threadIdx.x;      // float4 over 1M floats
    int row = idx >> 8, c4 = idx & 255;
    float4 v;
    if (c4 < 128) v = ((const float4*)(kW + (size_t)row*Hh))[c4];
    else          v = ((const float4*)(qW + (size_t)row*Hh))[c4 - 128];
    ((float4*)(W + (size_t)row*Cc))[c4] = v;
    if (idx < 256) {
        float4 bv;
        if (idx < 128) bv = ((const float4*)kb)[idx];
        else           bv = ((const float4*)qb)[idx - 128];
        ((float4*)bias)[idx] = bv;
    }
}

// =================================================================
// K1: partial logits. P[kc][b][l][n] = sum_{c in kc-half} X[b,n,c]*tok_W[c,l]
// grid (2 kc, 256 px-blocks) x 128; thread tile 4 px x 4 l. Bias added in k2.
// =================================================================
__global__ __launch_bounds__(128) void k1_proj(
    const float* __restrict__ X, const float* __restrict__ W,
    float* __restrict__ P)
{
    __shared__ float Xs[32][132];
    __shared__ float Ws[32][16];

    int tid = threadIdx.x;
    int kc  = blockIdx.x;                 // C-half
    int r0  = blockIdx.y * 128;           // pixel row base
    int b   = r0 >> 10;
    int n0  = r0 & 1023;
    int lg  = tid & 3;
    int pg  = tid >> 2;

    float2 acc[4][2];
#pragma unroll
    for (int i = 0; i < 4; i++) { acc[i][0] = make_float2(0.f,0.f); acc[i][1] = make_float2(0.f,0.f); }

    int kbeg = kc * 512;
    for (int k0 = kbeg; k0 < kbeg + 512; k0 += 32) {
        __syncthreads();
#pragma unroll
        for (int j = 0; j < 8; j++) {
            int v = tid + 128*j;
            int p = v >> 3, kq = v & 7;
            float4 f = *(const float4*)(X + (size_t)(r0 + p)*Cc + k0 + kq*4);
            Xs[kq*4+0][p] = f.x; Xs[kq*4+1][p] = f.y;
            Xs[kq*4+2][p] = f.z; Xs[kq*4+3][p] = f.w;
        }
        {
            int c = tid >> 2, lq = tid & 3;
            float4 wf = *(const float4*)(W + (size_t)(k0 + c)*Ll + lq*4);
            *(float4*)&Ws[c][lq*4] = wf;
        }
        __syncthreads();
#pragma unroll 8
        for (int kk = 0; kk < 32; kk++) {
            float4 xv = *(float4*)&Xs[kk][pg*4];
            float4 wv = *(float4*)&Ws[kk][lg*4];
            float2 w01 = make_float2(wv.x, wv.y), w23 = make_float2(wv.z, wv.w);
            float xr[4] = {xv.x, xv.y, xv.z, xv.w};
#pragma unroll
            for (int i = 0; i < 4; i++) {
                float2 ai = make_float2(xr[i], xr[i]);
                acc[i][0] = ffma2(ai, w01, acc[i][0]);
                acc[i][1] = ffma2(ai, w23, acc[i][1]);
            }
        }
    }
    float* Pp = P + (size_t)kc*BLC;
#pragma unroll
    for (int i = 0; i < 4; i++) {
        int n = n0 + pg*4 + i;
        float o[4] = {acc[i][0].x, acc[i][0].y, acc[i][1].x, acc[i][1].y};
#pragma unroll
        for (int j = 0; j < 4; j++) {
            int l = lg*4 + j;
            Pp[((b*Ll + l) << 10) + n] = o[j];
        }
    }
}

// =================================================================
// K2: reduce 2 k1-partials + bias, then softmax over n. grid 512 x 256.
// =================================================================
__global__ __launch_bounds__(256) void k2_softmax(
    const float* __restrict__ P, const float* __restrict__ tok_b,
    float* __restrict__ a)
{
    __shared__ float red[256];
    int row = blockIdx.x, tid = threadIdx.x;
    const float4* p0 = (const float4*)(P + ((size_t)row << 10));
    const float4* p1 = (const float4*)(P + (size_t)BLC + ((size_t)row << 10));
    float bl = tok_b[row & 15];
    float4 v = p0[tid], w = p1[tid];
    v.x += w.x + bl; v.y += w.y + bl; v.z += w.z + bl; v.w += w.w + bl;

    float m = fmaxf(fmaxf(v.x, v.y), fmaxf(v.z, v.w));
    red[tid] = m; __syncthreads();
    for (int s = 128; s > 0; s >>= 1) {
        if (tid < s) red[tid] = fmaxf(red[tid], red[tid+s]);
        __syncthreads();
    }
    float mx = red[0]; __syncthreads();

    v.x = __expf(v.x - mx); v.y = __expf(v.y - mx);
    v.z = __expf(v.z - mx); v.w = __expf(v.w - mx);
    red[tid] = v.x + v.y + v.z + v.w; __syncthreads();
    for (int s = 128; s > 0; s >>= 1) {
        if (tid < s) red[tid] += red[tid+s];
        __syncthreads();
    }
    float inv = 1.0f / red[0];
    v.x *= inv; v.y *= inv; v.z *= inv; v.w *= inv;
    ((float4*)(a + ((size_t)row << 10)))[tid] = v;
}

// =================================================================
// K3: partial T over 8 n-chunks of 128. grid (2 cx, 8 ny, 32 b) x 128.
// =================================================================
__global__ __launch_bounds__(128) void k3_aggregate(
    const float* __restrict__ X, const float* __restrict__ attn,
    float* __restrict__ Tp)
{
    __shared__ float As[128][16];
    int tid = threadIdx.x;
    int cx = blockIdx.x, ny = blockIdx.y, b = blockIdx.z;
    int n0 = ny * 128;

#pragma unroll
    for (int s = 0; s < 16; s++) {
        int v = tid + 128*s;
        int l = v >> 7, nn = v & 127;
        As[nn][l] = attn[((b*Ll + l) << 10) + n0 + nn];
    }
    __syncthreads();

    int c4 = cx*512 + tid*4;
    float2 acc[16][2];
#pragma unroll
    for (int l = 0; l < 16; l++) { acc[l][0] = make_float2(0.f,0.f); acc[l][1] = make_float2(0.f,0.f); }

    const float* Xb = X + (size_t)(b*Nn + n0)*Cc + c4;
#pragma unroll 4
    for (int nn = 0; nn < 128; nn++) {
        float4 xv = *(const float4*)(Xb + (size_t)nn*Cc);
        float2 x01 = make_float2(xv.x, xv.y), x23 = make_float2(xv.z, xv.w);
#pragma unroll
        for (int lq = 0; lq < 4; lq++) {
            float4 av = *(float4*)&As[nn][lq*4];
            float ar[4] = {av.x, av.y, av.z, av.w};
#pragma unroll
            for (int i = 0; i < 4; i++) {
                float2 a2 = make_float2(ar[i], ar[i]);
                int l = lq*4 + i;
                acc[l][0] = ffma2(a2, x01, acc[l][0]);
                acc[l][1] = ffma2(a2, x23, acc[l][1]);
            }
        }
    }
#pragma unroll
    for (int l = 0; l < 16; l++) {
        float4 o = make_float4(acc[l][0].x, acc[l][0].y, acc[l][1].x, acc[l][1].y);
        *(float4*)(Tp + (size_t)ny*BLC + ((b*Ll + l) << 10) + c4) = o;
    }
}

// K3b: T = sum of 8 partials. grid 512 x 256.
__global__ __launch_bounds__(256) void k3b_reduce(const float* __restrict__ Tp,
                                                  float* __restrict__ T)
{
    int idx = blockIdx.x*256 + threadIdx.x;
    const float4* p = (const float4*)Tp;
    float4 v = p[idx];
#pragma unroll
    for (int s = 1; s < 8; s++) {
        float4 t = p[idx + s*131072];
        v.x += t.x; v.y += t.y; v.z += t.z; v.w += t.w;
    }
    ((float4*)T)[idx] = v;
}

// =================================================================
// Chain GEMM v2: M=512, N=1024, K=1024, split-K=8 (slices of 128).
// BM=64, BN=128, BK=16; 128 threads; thread tile 8x8 (smem-balanced).
// grid dim3(8, 8, 8)
// =================================================================
__global__ __launch_bounds__(128) void gemm_sk(
    const float* __restrict__ A, const float* __restrict__ Bm,
    float* __restrict__ P, int transB)
{
    __shared__ float As[16][72];
    __shared__ float Bs[16][136];
    int tid = threadIdx.x;
    int n0 = blockIdx.x * 128, m0 = blockIdx.y * 64, s = blockIdx.z;
    int kbeg = s * 128;
    int tm = tid & 7, tn = tid >> 3;

    float2 acc[8][4];
#pragma unroll
    for (int i = 0; i < 8; i++)
#pragma unroll
        for (int j = 0; j < 4; j++) acc[i][j] = make_float2(0.f, 0.f);

    for (int k0 = kbeg; k0 < kbeg + 128; k0 += 16) {
        __syncthreads();
        // A: 64 x 16 transposed into As[k][m]
#pragma unroll
        for (int j = 0; j < 2; j++) {
            int v = tid + 128*j;
            int m = v >> 2, kq = v & 3;
            float4 f = *(const float4*)(A + (size_t)(m0 + m)*Cc + k0 + kq*4);
            As[kq*4+0][m] = f.x; As[kq*4+1][m] = f.y;
            As[kq*4+2][m] = f.z; As[kq*4+3][m] = f.w;
        }
        if (!transB) {
            // B: 16 x 128 direct
#pragma unroll
            for (int j = 0; j < 4; j++) {
                int v = tid + 128*j;
                int k = v >> 5, nq = v & 31;
                float4 f = *(const float4*)(Bm + (size_t)(k0 + k)*Cc + n0 + nq*4);
                *(float4*)&Bs[k][nq*4] = f;
            }
        } else {
            // B given as Bt[n][k]: scatter-transpose
#pragma unroll
            for (int j = 0; j < 4; j++) {
                int v = tid + 128*j;
                int n = v >> 2, kq = v & 3;
                float4 f = *(const float4*)(Bm + (size_t)(n0 + n)*Cc + k0 + kq*4);
                Bs[kq*4+0][n] = f.x; Bs[kq*4+1][n] = f.y;
                Bs[kq*4+2][n] = f.z; Bs[kq*4+3][n] = f.w;
            }
        }
        __syncthreads();
#pragma unroll
        for (int kk = 0; kk < 16; kk++) {
            float4 a0 = *(float4*)&As[kk][tm*8];
            float4 a1 = *(float4*)&As[kk][tm*8 + 4];
            float4 b0 = *(float4*)&Bs[kk][tn*8];
            float4 b1 = *(float4*)&Bs[kk][tn*8 + 4];
            float ar[8] = {a0.x, a0.y, a0.z, a0.w, a1.x, a1.y, a1.z, a1.w};
            float2 bp[4] = { make_float2(b0.x,b0.y), make_float2(b0.z,b0.w),
                             make_float2(b1.x,b1.y), make_float2(b1.z,b1.w) };
#pragma unroll
            for (int i = 0; i < 8; i++) {
                float2 ai = make_float2(ar[i], ar[i]);
#pragma unroll
                for (int j = 0; j < 4; j++)
                    acc[i][j] = ffma2(ai, bp[j], acc[i][j]);
            }
        }
    }

    float* Pp = P + (size_t)s*BLC;
#pragma unroll
    for (int i = 0; i < 8; i++) {
        int m = m0 + tm*8 + i;
        float* cp = Pp + (size_t)m*Cc + n0 + tn*8;
        *(float4*)cp       = make_float4(acc[i][0].x, acc[i][0].y, acc[i][1].x, acc[i][1].y);
        *(float4*)(cp + 4) = make_float4(acc[i][2].x, acc[i][2].y, acc[i][3].x, acc[i][3].y);
    }
}

// =================================================================
// GEMM epilogue: out = [res +] (relu)(sum_{s<8} P[s] + bias).
// Block = one output row (1024 floats). Optional fused cb[row] = qb . out_row.
// grid 512 x 256.
// =================================================================
__global__ __launch_bounds__(256) void gemm_fin(
    const float* __restrict__ P, const float* __restrict__ bias,
    const float* __restrict__ Res, float* __restrict__ out, int doRelu,
    const float* __restrict__ qb, float* __restrict__ cb)
{
    __shared__ float red[256];
    int row = blockIdx.x, tid = threadIdx.x;
    int idx = (row << 8) + tid;
    const float4* p = (const float4*)P;
    float4 v = p[idx];
#pragma unroll
    for (int s = 1; s < 8; s++) {
        float4 t = p[idx + s*131072];
        v.x += t.x; v.y += t.y; v.z += t.z; v.w += t.w;
    }
    if (bias) {
        float4 bv = ((const float4*)bias)[tid];
        v.x += bv.x; v.y += bv.y; v.z += bv.z; v.w += bv.w;
    }
    if (doRelu) {
        v.x = fmaxf(v.x, 0.f); v.y = fmaxf(v.y, 0.f);
        v.z = fmaxf(v.z, 0.f); v.w = fmaxf(v.w, 0.f);
    }
    if (Res) {
        float4 r = ((const float4*)Res)[idx];
        v.x += r.x; v.y += r.y; v.z += r.z; v.w += r.w;
    }
    ((float4*)out)[idx] = v;

    if (cb) {
        float4 qv = ((const float4*)qb)[tid];
        red[tid] = v.x*qv.x + v.y*qv.y + v.z*qv.z + v.w*qv.w;
        __syncthreads();
        for (int s = 128; s > 0; s >>= 1) {
            if (tid < s) red[tid] += red[tid+s];
            __syncthreads();
        }
        if (tid == 0) cb[row] = red[0];
    }
}

// =================================================================
// K5: per-batch token self-attention (k|q packed in kq rows).
// =================================================================
__global__ __launch_bounds__(256) void k5_attn(
    const float* __restrict__ kq, const float* __restrict__ T,
    float* __restrict__ Td)
{
    __shared__ float sc[16][16];
    __shared__ float aw[16][16];
    int b = blockIdx.x, tid = threadIdx.x;
    int i = tid >> 4, j = tid & 15;

    const float4* kr = (const float4*)(kq + (size_t)(b*Ll + i)*Cc);
    const float4* qr = (const float4*)(kq + (size_t)(b*Ll + j)*Cc + Hh);
    float s = 0.f;
#pragma unroll 8
    for (int t = 0; t < 128; t++) {
        float4 kv = kr[t], qv = qr[t];
        s += kv.x*qv.x + kv.y*qv.y + kv.z*qv.z + kv.w*qv.w;
    }
    sc[i][j] = s;
    __syncthreads();

    if (tid < 16) {
        float m = -1e30f;
#pragma unroll
        for (int jj = 0; jj < 16; jj++) m = fmaxf(m, sc[tid][jj]);
        float sum = 0.f;
        float e[16];
#pragma unroll
        for (int jj = 0; jj < 16; jj++) { e[jj] = __expf(sc[tid][jj] - m); sum += e[jj]; }
        float inv = 1.f/sum;
#pragma unroll
        for (int jj = 0; jj < 16; jj++) aw[tid][jj] = e[jj]*inv;
    }
    __syncthreads();

    const float4* Tb = (const float4*)(T + (size_t)b*Ll*Cc);
    float4* Tdb = (float4*)(Td + (size_t)b*Ll*Cc);
#pragma unroll
    for (int t = 0; t < 16; t++) {
        int v = tid + 256*t;
        int ii = v >> 8, c4 = v & 255;
        float4 o = Tb[(ii << 8) + c4];
#pragma unroll
        for (int jj = 0; jj < 16; jj++) {
            float a = aw[ii][jj];
            float4 tv = Tb[(jj << 8) + c4];
            o.x += a*tv.x; o.y += a*tv.y; o.z += a*tv.z; o.w += a*tv.w;
        }
        Tdb[(ii << 8) + c4] = o;
    }
}

// =================================================================
// K10: projector pixel pass (packed FMA).
// =================================================================
__global__ __launch_bounds__(256) void k10_pixels(
    const float* __restrict__ X, const float* __restrict__ U,
    const float* __restrict__ Tout, const float* __restrict__ cb,
    float* __restrict__ Xout)
{
    extern __shared__ float sm[];
    float* Us = sm;
    float* Ts = sm + 16384;
    float* cbs = sm + 32768;

    int b  = blockIdx.x >> 4;
    int pb = blockIdx.x & 15;
    int tid = threadIdx.x;

    {
        const float4* u4 = (const float4*)(U + (size_t)b*16384);
        const float4* t4 = (const float4*)(Tout + (size_t)b*16384);
        float4* us4 = (float4*)Us; float4* ts4 = (float4*)Ts;
#pragma unroll
        for (int j = 0; j < 16; j++) {
            int idx = tid + 256*j;
            us4[idx] = u4[idx];
            ts4[idx] = t4[idx];
        }
        if (tid < 16) cbs[tid] = cb[b*Ll + tid];
    }
    __syncthreads();

    int w = tid >> 5, lane = tid & 31;
    for (int it = 0; it < 2; it++) {
        int p0 = pb*64 + it*32 + w*4;
        const float4* Xp = (const float4*)(X + (size_t)(b*Nn + p0)*Cc);
        float2 acc2[4][16];
#pragma unroll
        for (int p = 0; p < 4; p++)
#pragma unroll
            for (int l = 0; l < 16; l++) acc2[p][l] = make_float2(0.f, 0.f);

#pragma unroll
        for (int j = 0; j < 8; j++) {
            int c4 = lane + 32*j;
            float2 x01[4], x23[4];
#pragma unroll
            for (int p = 0; p < 4; p++) {
                float4 xv = Xp[(p << 8) + c4];
                x01[p] = make_float2(xv.x, xv.y);
                x23[p] = make_float2(xv.z, xv.w);
            }
#pragma unroll
            for (int l = 0; l < 16; l++) {
                float4 uv = ((float4*)(Us + (l << 10)))[c4];
                float2 u01 = make_float2(uv.x, uv.y), u23 = make_float2(uv.z, uv.w);
#pragma unroll
                for (int p = 0; p < 4; p++) {
                    acc2[p][l] = ffma2(x01[p], u01, acc2[p][l]);
                    acc2[p][l] = ffma2(x23[p], u23, acc2[p][l]);
                }
            }
        }
        float acc[4][16];
#pragma unroll
        for (int p = 0; p < 4; p++)
#pragma unroll
            for (int l = 0; l < 16; l++) acc[p][l] = acc2[p][l].x + acc2[p][l].y;

#pragma unroll
        for (int off = 16; off > 0; off >>= 1)
#pragma unroll
            for (int p = 0; p < 4; p++)
#pragma unroll
                for (int l = 0; l < 16; l++)
                    acc[p][l] += __shfl_xor_sync(0xFFFFFFFFu, acc[p][l], off);

#pragma unroll
        for (int p = 0; p < 4; p++) {
            float m = -1e30f;
#pragma unroll
            for (int l = 0; l < 16; l++) {
                acc[p][l] += cbs[l];
                m = fmaxf(m, acc[p][l]);
            }
            float s = 0.f;
#pragma unroll
            for (int l = 0; l < 16; l++) { acc[p][l] = __expf(acc[p][l] - m); s += acc[p][l]; }
            float inv = 1.f/s;
#pragma unroll
            for (int l = 0; l < 16; l++) acc[p][l] *= inv;
        }

        float4* Op = (float4*)(Xout + (size_t)(b*Nn + p0)*Cc);
#pragma unroll
        for (int j = 0; j < 8; j++) {
            int c4 = lane + 32*j;
            float2 o01[4], o23[4];
#pragma unroll
            for (int p = 0; p < 4; p++) {
                float4 xv = Xp[(p << 8) + c4];
                o01[p] = make_float2(xv.x, xv.y);
                o23[p] = make_float2(xv.z, xv.w);
            }
#pragma unroll
            for (int l = 0; l < 16; l++) {
                float4 tv = ((float4*)(Ts + (l << 10)))[c4];
                float2 t01 = make_float2(tv.x, tv.y), t23 = make_float2(tv.z, tv.w);
#pragma unroll
                for (int p = 0; p < 4; p++) {
                    float2 a2 = make_float2(acc[p][l], acc[p][l]);
                    o01[p] = ffma2(a2, t01, o01[p]);
                    o23[p] = ffma2(a2, t23, o23[p]);
                }
            }
#pragma unroll
            for (int p = 0; p < 4; p++)
                Op[(p << 8) + c4] = make_float4(o01[p].x, o01[p].y, o23[p].x, o23[p].y);
        }
    }
}

// =================================================================
extern "C" void kernel_launch(void* const* d_in, const int* in_sizes, int n_in,
                              void* d_out, int out_size)
{
    const float* X       = (const float*)d_in[0];
    const float* tok_W   = (const float*)d_in[2];
    const float* tok_b   = (const float*)d_in[3];
    const float* key_W   = (const float*)d_in[4];
    const float* key_b   = (const float*)d_in[5];
    const float* query_W = (const float*)d_in[6];
    const float* query_b = (const float*)d_in[7];
    const float* f1_W    = (const float*)d_in[8];
    const float* f1_b    = (const float*)d_in[9];
    const float* f2_W    = (const float*)d_in[10];
    const float* f2_b    = (const float*)d_in[11];
    const float* q_W     = (const float*)d_in[12];
    const float* q_b     = (const float*)d_in[13];
    const float* k_W     = (const float*)d_in[14];
    const float* k_b     = (const float*)d_in[15];

    float* Xout = (float*)d_out;
    float* Tout = (float*)d_out + (size_t)BNC;

    float *p_attn, *p_T, *p_Tp, *p_kq, *p_Td, *p_h, *p_TK, *p_U, *p_cb, *p_Wkq, *p_bkq;
    cudaGetSymbolAddress((void**)&p_attn, g_attn);
    cudaGetSymbolAddress((void**)&p_T,    g_T);
    cudaGetSymbolAddress((void**)&p_Tp,   g_Tp);
    cudaGetSymbolAddress((void**)&p_kq,   g_kq);
    cudaGetSymbolAddress((void**)&p_Td,   g_Td);
    cudaGetSymbolAddress((void**)&p_h,    g_h);
    cudaGetSymbolAddress((void**)&p_TK,   g_TK);
    cudaGetSymbolAddress((void**)&p_U,    g_U);
    cudaGetSymbolAddress((void**)&p_cb,   g_cb);
    cudaGetSymbolAddress((void**)&p_Wkq,  g_Wkq);
    cudaGetSymbolAddress((void**)&p_bkq,  g_bkq);

    cudaFuncSetAttribute(k10_pixels,
        cudaFuncAttributeMaxDynamicSharedMemorySize, (32768 + 16) * 4);

    // Phase A: tokenizer
    k_pack_kq<<<1024, 256>>>(key_W, key_b, query_W, query_b, p_Wkq, p_bkq);
    k1_proj<<<dim3(2, 256), 128>>>(X, tok_W, p_Tp);
    k2_softmax<<<512, 256>>>(p_Tp, tok_b, p_attn);
    k3_aggregate<<<dim3(2, 8, 32), 128>>>(X, p_attn, p_Tp);
    k3b_reduce<<<512, 256>>>(p_Tp, p_T);

    // Phase B: token transformer (split-K GEMMs + epilogues)
    gemm_sk<<<dim3(8, 8, 8), 128>>>(p_T, p_Wkq, p_Tp, 0);
    gemm_fin<<<512, 256>>>(p_Tp, p_bkq, nullptr, p_kq, 0, nullptr, nullptr);
    k5_attn<<<32, 256>>>(p_kq, p_T, p_Td);
    gemm_sk<<<dim3(8, 8, 8), 128>>>(p_Td, f1_W, p_Tp, 0);
    gemm_fin<<<512, 256>>>(p_Tp, f1_b, nullptr, p_h, 1, nullptr, nullptr);
    gemm_sk<<<dim3(8, 8, 8), 128>>>(p_h, f2_W, p_Tp, 0);
    gemm_fin<<<512, 256>>>(p_Tp, f2_b, p_Td, Tout, 0, nullptr, nullptr);

    // Projector token-side transforms (cb fused into TK epilogue)
    gemm_sk<<<dim3(8, 8, 8), 128>>>(Tout, k_W, p_Tp, 0);
    gemm_fin<<<512, 256>>>(p_Tp, k_b, nullptr, p_TK, 0, q_b, p_cb);
    gemm_sk<<<dim3(8, 8, 8), 128>>>(p_TK, q_W, p_Tp, 1);
    gemm_fin<<<512, 256>>>(p_Tp, nullptr, nullptr, p_U, 0, nullptr, nullptr);

    // Phase C: pixel pass
    k10_pixels<<<512, 256, (32768 + 16) * 4>>>(X, p_U, Tout, p_cb, Xout);

    (void)in_sizes; (void)n_in; (void)out_size;
}

// round 9
// speedup vs baseline: 1.1077x; 1.1077x over previous
#include <cuda_runtime.h>
#include <cstdint>

// ---------------- problem dims ----------------
#define Bb 32
#define Nn 1024
#define Cc 1024
#define Ll 16
#define Hh 512
#define BNC (Bb*Nn*Cc)       // 33554432
#define BLC (Bb*Ll*Cc)       // 524288 (== B*L*N == chain GEMM size MN)

// ---------------- packed f32x2 FMA (sm_103a FFMA2, PTX-only) ----------------
union F2U { float2 f; unsigned long long u; };
__device__ __forceinline__ float2 ffma2(float2 a, float2 b, float2 c)
{
    F2U ua, ub, uc, ud;
    ua.f = a; ub.f = b; uc.f = c;
    asm("fma.rn.f32x2 %0, %1, %2, %3;"
        : "=l"(ud.u) : "l"(ua.u), "l"(ub.u), "l"(uc.u));
    return ud.f;
}

// ---------------- scratch ----------------
__device__ float g_attn[Bb*Ll*Nn];   // softmax weights, [b][l][n]
__device__ float g_T[BLC];           // tokens [b][l][c]
__device__ float g_Tp[16*BLC];       // partial scratch: k1(4), k3(16), gemm split-K(8)
__device__ float g_kq[BLC];          // [token][0:512]=k, [512:1024]=q
__device__ float g_Td[BLC];          // T_dash
__device__ float g_h[BLC];           // relu(f1)
__device__ float g_TK[BLC];          // T_out @ k_W + k_b
__device__ float g_U[BLC];           // TK @ q_W^T
__device__ float g_cb[Bb*Ll];        // q_b . TK[b,l]
__device__ float g_Wkq[Cc*Cc];       // [key_W | query_W]
__device__ float g_bkq[Cc];          // [key_b | query_b]

// =================================================================
// pack key/query weights into one [1024][1024] matrix + bias
// =================================================================
__global__ __launch_bounds__(256) void k_pack_kq(
    const float* __restrict__ kW, const float* __restrict__ kb,
    const float* __restrict__ qW, const float* __restrict__ qb,
    float* __restrict__ W, float* __restrict__ bias)
{
    int idx = blockIdx.x*256 + threadIdx.x;      // float4 over 1M floats
    int row = idx >> 8, c4 = idx & 255;
    float4 v;
    if (c4 < 128) v = ((const float4*)(kW + (size_t)row*Hh))[c4];
    else          v = ((const float4*)(qW + (size_t)row*Hh))[c4 - 128];
    ((float4*)(W + (size_t)row*Cc))[c4] = v;
    if (idx < 256) {
        float4 bv;
        if (idx < 128) bv = ((const float4*)kb)[idx];
        else           bv = ((const float4*)qb)[idx - 128];
        ((float4*)bias)[idx] = bv;
    }
}

// =================================================================
// K1: partial logits over 4 C-quarters. grid (4 kc, 256 px) x 128.
// P[kc][b][l][n] = sum_{c in quarter} X[b,n,c]*tok_W[c,l]; bias in k2.
// =================================================================
__global__ __launch_bounds__(128) void k1_proj(
    const float* __restrict__ X, const float* __restrict__ W,
    float* __restrict__ P)
{
    __shared__ float Xs[32][132];
    __shared__ float Ws[32][16];

    int tid = threadIdx.x;
    int kc  = blockIdx.x;                 // C-quarter
    int r0  = blockIdx.y * 128;           // pixel row base
    int b   = r0 >> 10;
    int n0  = r0 & 1023;
    int lg  = tid & 3;
    int pg  = tid >> 2;

    float2 acc[4][2];
#pragma unroll
    for (int i = 0; i < 4; i++) { acc[i][0] = make_float2(0.f,0.f); acc[i][1] = make_float2(0.f,0.f); }

    int kbeg = kc * 256;
    for (int k0 = kbeg; k0 < kbeg + 256; k0 += 32) {
        __syncthreads();
#pragma unroll
        for (int j = 0; j < 8; j++) {
            int v = tid + 128*j;
            int p = v >> 3, kq = v & 7;
            float4 f = *(const float4*)(X + (size_t)(r0 + p)*Cc + k0 + kq*4);
            Xs[kq*4+0][p] = f.x; Xs[kq*4+1][p] = f.y;
            Xs[kq*4+2][p] = f.z; Xs[kq*4+3][p] = f.w;
        }
        {
            int c = tid >> 2, lq = tid & 3;
            float4 wf = *(const float4*)(W + (size_t)(k0 + c)*Ll + lq*4);
            *(float4*)&Ws[c][lq*4] = wf;
        }
        __syncthreads();
#pragma unroll 8
        for (int kk = 0; kk < 32; kk++) {
            float4 xv = *(float4*)&Xs[kk][pg*4];
            float4 wv = *(float4*)&Ws[kk][lg*4];
            float2 w01 = make_float2(wv.x, wv.y), w23 = make_float2(wv.z, wv.w);
            float xr[4] = {xv.x, xv.y, xv.z, xv.w};
#pragma unroll
            for (int i = 0; i < 4; i++) {
                float2 ai = make_float2(xr[i], xr[i]);
                acc[i][0] = ffma2(ai, w01, acc[i][0]);
                acc[i][1] = ffma2(ai, w23, acc[i][1]);
            }
        }
    }
    float* Pp = P + (size_t)kc*BLC;
#pragma unroll
    for (int i = 0; i < 4; i++) {
        int n = n0 + pg*4 + i;
        float o[4] = {acc[i][0].x, acc[i][0].y, acc[i][1].x, acc[i][1].y};
#pragma unroll
        for (int j = 0; j < 4; j++) {
            int l = lg*4 + j;
            Pp[((b*Ll + l) << 10) + n] = o[j];
        }
    }
}

// =================================================================
// K2: reduce 4 k1-partials + bias, then softmax over n. grid 512 x 256.
// =================================================================
__global__ __launch_bounds__(256) void k2_softmax(
    const float* __restrict__ P, const float* __restrict__ tok_b,
    float* __restrict__ a)
{
    __shared__ float red[256];
    int row = blockIdx.x, tid = threadIdx.x;
    size_t ro = (size_t)row << 10;
    const float4* p0 = (const float4*)(P + ro);
    const float4* p1 = (const float4*)(P + (size_t)BLC + ro);
    const float4* p2 = (const float4*)(P + 2*(size_t)BLC + ro);
    const float4* p3 = (const float4*)(P + 3*(size_t)BLC + ro);
    float bl = tok_b[row & 15];
    float4 v = p0[tid], w1 = p1[tid], w2 = p2[tid], w3 = p3[tid];
    v.x += w1.x + w2.x + w3.x + bl;
    v.y += w1.y + w2.y + w3.y + bl;
    v.z += w1.z + w2.z + w3.z + bl;
    v.w += w1.w + w2.w + w3.w + bl;

    float m = fmaxf(fmaxf(v.x, v.y), fmaxf(v.z, v.w));
    red[tid] = m; __syncthreads();
    for (int s = 128; s > 0; s >>= 1) {
        if (tid < s) red[tid] = fmaxf(red[tid], red[tid+s]);
        __syncthreads();
    }
    float mx = red[0]; __syncthreads();

    v.x = __expf(v.x - mx); v.y = __expf(v.y - mx);
    v.z = __expf(v.z - mx); v.w = __expf(v.w - mx);
    red[tid] = v.x + v.y + v.z + v.w; __syncthreads();
    for (int s = 128; s > 0; s >>= 1) {
        if (tid < s) red[tid] += red[tid+s];
        __syncthreads();
    }
    float inv = 1.0f / red[0];
    v.x *= inv; v.y *= inv; v.z *= inv; v.w *= inv;
    ((float4*)(a + ro))[tid] = v;
}

// =================================================================
// K3: partial T over 16 n-chunks of 64. grid (2 cx, 16 ny, 32 b) x 128.
// =================================================================
__global__ __launch_bounds__(128) void k3_aggregate(
    const float* __restrict__ X, const float* __restrict__ attn,
    float* __restrict__ Tp)
{
    __shared__ float As[64][16];
    int tid = threadIdx.x;
    int cx = blockIdx.x, ny = blockIdx.y, b = blockIdx.z;
    int n0 = ny * 64;

#pragma unroll
    for (int s = 0; s < 8; s++) {
        int v = tid + 128*s;
        int l = v >> 6, nn = v & 63;
        As[nn][l] = attn[((b*Ll + l) << 10) + n0 + nn];
    }
    __syncthreads();

    int c4 = cx*512 + tid*4;
    float2 acc[16][2];
#pragma unroll
    for (int l = 0; l < 16; l++) { acc[l][0] = make_float2(0.f,0.f); acc[l][1] = make_float2(0.f,0.f); }

    const float* Xb = X + (size_t)(b*Nn + n0)*Cc + c4;
#pragma unroll 4
    for (int nn = 0; nn < 64; nn++) {
        float4 xv = *(const float4*)(Xb + (size_t)nn*Cc);
        float2 x01 = make_float2(xv.x, xv.y), x23 = make_float2(xv.z, xv.w);
#pragma unroll
        for (int lq = 0; lq < 4; lq++) {
            float4 av = *(float4*)&As[nn][lq*4];
            float ar[4] = {av.x, av.y, av.z, av.w};
#pragma unroll
            for (int i = 0; i < 4; i++) {
                float2 a2 = make_float2(ar[i], ar[i]);
                int l = lq*4 + i;
                acc[l][0] = ffma2(a2, x01, acc[l][0]);
                acc[l][1] = ffma2(a2, x23, acc[l][1]);
            }
        }
    }
#pragma unroll
    for (int l = 0; l < 16; l++) {
        float4 o = make_float4(acc[l][0].x, acc[l][0].y, acc[l][1].x, acc[l][1].y);
        *(float4*)(Tp + (size_t)ny*BLC + ((b*Ll + l) << 10) + c4) = o;
    }
}

// K3b: T = sum of 16 partials. grid 512 x 256.
__global__ __launch_bounds__(256) void k3b_reduce(const float* __restrict__ Tp,
                                                  float* __restrict__ T)
{
    int idx = blockIdx.x*256 + threadIdx.x;
    const float4* p = (const float4*)Tp;
    float4 v = p[idx];
#pragma unroll
    for (int s = 1; s < 16; s++) {
        float4 t = p[idx + s*131072];
        v.x += t.x; v.y += t.y; v.z += t.z; v.w += t.w;
    }
    ((float4*)T)[idx] = v;
}

// =================================================================
// Chain GEMM v3b: M=512, N=1024, K=1024, split-K=8 (slices of 128).
// BM=64, BN=128, BK=16; 128 threads; thread tile 8x8.
// A swizzle mc = m + (m>>3)*4: fragment base tm*12 words = 48B*tm
// (16B-aligned), phase banks {0,12,24,4,16,28,8,20} -> conflict-free.
// grid dim3(8, 8, 8)
// =================================================================
__global__ __launch_bounds__(128) void gemm_sk(
    const float* __restrict__ A, const float* __restrict__ Bm,
    float* __restrict__ P, int transB)
{
    __shared__ float As[16][96];     // 64 m + 4 pad per 8-m group (max col 91)
    __shared__ float Bs[16][136];
    int tid = threadIdx.x;
    int n0 = blockIdx.x * 128, m0 = blockIdx.y * 64, s = blockIdx.z;
    int kbeg = s * 128;
    int tm = tid & 7, tn = tid >> 3;

    float2 acc[8][4];
#pragma unroll
    for (int i = 0; i < 8; i++)
#pragma unroll
        for (int j = 0; j < 4; j++) acc[i][j] = make_float2(0.f, 0.f);

    for (int k0 = kbeg; k0 < kbeg + 128; k0 += 16) {
        __syncthreads();
        // A: 64 x 16 transposed into As[k][mc], mc = m + (m>>3)*4
#pragma unroll
        for (int j = 0; j < 2; j++) {
            int v = tid + 128*j;
            int m = v >> 2, kq = v & 3;
            int mc = m + ((m >> 3) << 2);
            float4 f = *(const float4*)(A + (size_t)(m0 + m)*Cc + k0 + kq*4);
            As[kq*4+0][mc] = f.x; As[kq*4+1][mc] = f.y;
            As[kq*4+2][mc] = f.z; As[kq*4+3][mc] = f.w;
        }
        if (!transB) {
            // B: 16 x 128 direct
#pragma unroll
            for (int j = 0; j < 4; j++) {
                int v = tid + 128*j;
                int k = v >> 5, nq = v & 31;
                float4 f = *(const float4*)(Bm + (size_t)(k0 + k)*Cc + n0 + nq*4);
                *(float4*)&Bs[k][nq*4] = f;
            }
        } else {
            // B given as Bt[n][k]: scatter-transpose
#pragma unroll
            for (int j = 0; j < 4; j++) {
                int v = tid + 128*j;
                int n = v >> 2, kq = v & 3;
                float4 f = *(const float4*)(Bm + (size_t)(n0 + n)*Cc + k0 + kq*4);
                Bs[kq*4+0][n] = f.x; Bs[kq*4+1][n] = f.y;
                Bs[kq*4+2][n] = f.z; Bs[kq*4+3][n] = f.w;
            }
        }
        __syncthreads();
        int tms = tm * 12;    // swizzled fragment base (16B-aligned)
#pragma unroll
        for (int kk = 0; kk < 16; kk++) {
            float4 a0 = *(float4*)&As[kk][tms];
            float4 a1 = *(float4*)&As[kk][tms + 4];
            float4 b0 = *(float4*)&Bs[kk][tn*8];
            float4 b1 = *(float4*)&Bs[kk][tn*8 + 4];
            float ar[8] = {a0.x, a0.y, a0.z, a0.w, a1.x, a1.y, a1.z, a1.w};
            float2 bp[4] = { make_float2(b0.x,b0.y), make_float2(b0.z,b0.w),
                             make_float2(b1.x,b1.y), make_float2(b1.z,b1.w) };
#pragma unroll
            for (int i = 0; i < 8; i++) {
                float2 ai = make_float2(ar[i], ar[i]);
#pragma unroll
                for (int j = 0; j < 4; j++)
                    acc[i][j] = ffma2(ai, bp[j], acc[i][j]);
            }
        }
    }

    float* Pp = P + (size_t)s*BLC;
#pragma unroll
    for (int i = 0; i < 8; i++) {
        int m = m0 + tm*8 + i;
        float* cp = Pp + (size_t)m*Cc + n0 + tn*8;
        *(float4*)cp       = make_float4(acc[i][0].x, acc[i][0].y, acc[i][1].x, acc[i][1].y);
        *(float4*)(cp + 4) = make_float4(acc[i][2].x, acc[i][2].y, acc[i][3].x, acc[i][3].y);
    }
}

// =================================================================
// GEMM epilogue: out = [res +] (relu)(sum_{s<8} P[s] + bias).
// Block = one output row. Optional fused cb[row] = qb . out_row.
// grid 512 x 256.
// =================================================================
__global__ __launch_bounds__(256) void gemm_fin(
    const float* __restrict__ P, const float* __restrict__ bias,
    const float* __restrict__ Res, float* __restrict__ out, int doRelu,
    const float* __restrict__ qb, float* __restrict__ cb)
{
    __shared__ float red[256];
    int row = blockIdx.x, tid = threadIdx.x;
    int idx = (row << 8) + tid;
    const float4* p = (const float4*)P;
    float4 v = p[idx];
#pragma unroll
    for (int s = 1; s < 8; s++) {
        float4 t = p[idx + s*131072];
        v.x += t.x; v.y += t.y; v.z += t.z; v.w += t.w;
    }
    if (bias) {
        float4 bv = ((const float4*)bias)[tid];
        v.x += bv.x; v.y += bv.y; v.z += bv.z; v.w += bv.w;
    }
    if (doRelu) {
        v.x = fmaxf(v.x, 0.f); v.y = fmaxf(v.y, 0.f);
        v.z = fmaxf(v.z, 0.f); v.w = fmaxf(v.w, 0.f);
    }
    if (Res) {
        float4 r = ((const float4*)Res)[idx];
        v.x += r.x; v.y += r.y; v.z += r.z; v.w += r.w;
    }
    ((float4*)out)[idx] = v;

    if (cb) {
        float4 qv = ((const float4*)qb)[tid];
        red[tid] = v.x*qv.x + v.y*qv.y + v.z*qv.z + v.w*qv.w;
        __syncthreads();
        for (int s = 128; s > 0; s >>= 1) {
            if (tid < s) red[tid] += red[tid+s];
            __syncthreads();
        }
        if (tid == 0) cb[row] = red[0];
    }
}

// =================================================================
// K5: per-batch token self-attention (k|q packed in kq rows).
// =================================================================
__global__ __launch_bounds__(256) void k5_attn(
    const float* __restrict__ kq, const float* __restrict__ T,
    float* __restrict__ Td)
{
    __shared__ float sc[16][16];
    __shared__ float aw[16][16];
    int b = blockIdx.x, tid = threadIdx.x;
    int i = tid >> 4, j = tid & 15;

    const float4* kr = (const float4*)(kq + (size_t)(b*Ll + i)*Cc);
    const float4* qr = (const float4*)(kq + (size_t)(b*Ll + j)*Cc + Hh);
    float s = 0.f;
#pragma unroll 8
    for (int t = 0; t < 128; t++) {
        float4 kv = kr[t], qv = qr[t];
        s += kv.x*qv.x + kv.y*qv.y + kv.z*qv.z + kv.w*qv.w;
    }
    sc[i][j] = s;
    __syncthreads();

    if (tid < 16) {
        float m = -1e30f;
#pragma unroll
        for (int jj = 0; jj < 16; jj++) m = fmaxf(m, sc[tid][jj]);
        float sum = 0.f;
        float e[16];
#pragma unroll
        for (int jj = 0; jj < 16; jj++) { e[jj] = __expf(sc[tid][jj] - m); sum += e[jj]; }
        float inv = 1.f/sum;
#pragma unroll
        for (int jj = 0; jj < 16; jj++) aw[tid][jj] = e[jj]*inv;
    }
    __syncthreads();

    const float4* Tb = (const float4*)(T + (size_t)b*Ll*Cc);
    float4* Tdb = (float4*)(Td + (size_t)b*Ll*Cc);
#pragma unroll
    for (int t = 0; t < 16; t++) {
        int v = tid + 256*t;
        int ii = v >> 8, c4 = v & 255;
        float4 o = Tb[(ii << 8) + c4];
#pragma unroll
        for (int jj = 0; jj < 16; jj++) {
            float a = aw[ii][jj];
            float4 tv = Tb[(jj << 8) + c4];
            o.x += a*tv.x; o.y += a*tv.y; o.z += a*tv.z; o.w += a*tv.w;
        }
        Tdb[(ii << 8) + c4] = o;
    }
}

// =================================================================
// K10: projector pixel pass (packed FMA).
// =================================================================
__global__ __launch_bounds__(256) void k10_pixels(
    const float* __restrict__ X, const float* __restrict__ U,
    const float* __restrict__ Tout, const float* __restrict__ cb,
    float* __restrict__ Xout)
{
    extern __shared__ float sm[];
    float* Us = sm;
    float* Ts = sm + 16384;
    float* cbs = sm + 32768;

    int b  = blockIdx.x >> 4;
    int pb = blockIdx.x & 15;
    int tid = threadIdx.x;

    {
        const float4* u4 = (const float4*)(U + (size_t)b*16384);
        const float4* t4 = (const float4*)(Tout + (size_t)b*16384);
        float4* us4 = (float4*)Us; float4* ts4 = (float4*)Ts;
#pragma unroll
        for (int j = 0; j < 16; j++) {
            int idx = tid + 256*j;
            us4[idx] = u4[idx];
            ts4[idx] = t4[idx];
        }
        if (tid < 16) cbs[tid] = cb[b*Ll + tid];
    }
    __syncthreads();

    int w = tid >> 5, lane = tid & 31;
    for (int it = 0; it < 2; it++) {
        int p0 = pb*64 + it*32 + w*4;
        const float4* Xp = (const float4*)(X + (size_t)(b*Nn + p0)*Cc);
        float2 acc2[4][16];
#pragma unroll
        for (int p = 0; p < 4; p++)
#pragma unroll
            for (int l = 0; l < 16; l++) acc2[p][l] = make_float2(0.f, 0.f);

#pragma unroll
        for (int j = 0; j < 8; j++) {
            int c4 = lane + 32*j;
            float2 x01[4], x23[4];
#pragma unroll
            for (int p = 0; p < 4; p++) {
                float4 xv = Xp[(p << 8) + c4];
                x01[p] = make_float2(xv.x, xv.y);
                x23[p] = make_float2(xv.z, xv.w);
            }
#pragma unroll
            for (int l = 0; l < 16; l++) {
                float4 uv = ((float4*)(Us + (l << 10)))[c4];
                float2 u01 = make_float2(uv.x, uv.y), u23 = make_float2(uv.z, uv.w);
#pragma unroll
                for (int p = 0; p < 4; p++) {
                    acc2[p][l] = ffma2(x01[p], u01, acc2[p][l]);
                    acc2[p][l] = ffma2(x23[p], u23, acc2[p][l]);
                }
            }
        }
        float acc[4][16];
#pragma unroll
        for (int p = 0; p < 4; p++)
#pragma unroll
            for (int l = 0; l < 16; l++) acc[p][l] = acc2[p][l].x + acc2[p][l].y;

#pragma unroll
        for (int off = 16; off > 0; off >>= 1)
#pragma unroll
            for (int p = 0; p < 4; p++)
#pragma unroll
                for (int l = 0; l < 16; l++)
                    acc[p][l] += __shfl_xor_sync(0xFFFFFFFFu, acc[p][l], off);

#pragma unroll
        for (int p = 0; p < 4; p++) {
            float m = -1e30f;
#pragma unroll
            for (int l = 0; l < 16; l++) {
                acc[p][l] += cbs[l];
                m = fmaxf(m, acc[p][l]);
            }
            float s = 0.f;
#pragma unroll
            for (int l = 0; l < 16; l++) { acc[p][l] = __expf(acc[p][l] - m); s += acc[p][l]; }
            float inv = 1.f/s;
#pragma unroll
            for (int l = 0; l < 16; l++) acc[p][l] *= inv;
        }

        float4* Op = (float4*)(Xout + (size_t)(b*Nn + p0)*Cc);
#pragma unroll
        for (int j = 0; j < 8; j++) {
            int c4 = lane + 32*j;
            float2 o01[4], o23[4];
#pragma unroll
            for (int p = 0; p < 4; p++) {
                float4 xv = Xp[(p << 8) + c4];
                o01[p] = make_float2(xv.x, xv.y);
                o23[p] = make_float2(xv.z, xv.w);
            }
#pragma unroll
            for (int l = 0; l < 16; l++) {
                float4 tv = ((float4*)(Ts + (l << 10)))[c4];
                float2 t01 = make_float2(tv.x, tv.y), t23 = make_float2(tv.z, tv.w);
#pragma unroll
                for (int p = 0; p < 4; p++) {
                    float2 a2 = make_float2(acc[p][l], acc[p][l]);
                    o01[p] = ffma2(a2, t01, o01[p]);
                    o23[p] = ffma2(a2, t23, o23[p]);
                }
            }
#pragma unroll
            for (int p = 0; p < 4; p++)
                Op[(p << 8) + c4] = make_float4(o01[p].x, o01[p].y, o23[p].x, o23[p].y);
        }
    }
}

// =================================================================
extern "C" void kernel_launch(void* const* d_in, const int* in_sizes, int n_in,
                              void* d_out, int out_size)
{
    const float* X       = (const float*)d_in[0];
    const float* tok_W   = (const float*)d_in[2];
    const float* tok_b   = (const float*)d_in[3];
    const float* key_W   = (const float*)d_in[4];
    const float* key_b   = (const float*)d_in[5];
    const float* query_W = (const float*)d_in[6];
    const float* query_b = (const float*)d_in[7];
    const float* f1_W    = (const float*)d_in[8];
    const float* f1_b    = (const float*)d_in[9];
    const float* f2_W    = (const float*)d_in[10];
    const float* f2_b    = (const float*)d_in[11];
    const float* q_W     = (const float*)d_in[12];
    const float* q_b     = (const float*)d_in[13];
    const float* k_W     = (const float*)d_in[14];
    const float* k_b     = (const float*)d_in[15];

    float* Xout = (float*)d_out;
    float* Tout = (float*)d_out + (size_t)BNC;

    float *p_attn, *p_T, *p_Tp, *p_kq, *p_Td, *p_h, *p_TK, *p_U, *p_cb, *p_Wkq, *p_bkq;
    cudaGetSymbolAddress((void**)&p_attn, g_attn);
    cudaGetSymbolAddress((void**)&p_T,    g_T);
    cudaGetSymbolAddress((void**)&p_Tp,   g_Tp);
    cudaGetSymbolAddress((void**)&p_kq,   g_kq);
    cudaGetSymbolAddress((void**)&p_Td,   g_Td);
    cudaGetSymbolAddress((void**)&p_h,    g_h);
    cudaGetSymbolAddress((void**)&p_TK,   g_TK);
    cudaGetSymbolAddress((void**)&p_U,    g_U);
    cudaGetSymbolAddress((void**)&p_cb,   g_cb);
    cudaGetSymbolAddress((void**)&p_Wkq,  g_Wkq);
    cudaGetSymbolAddress((void**)&p_bkq,  g_bkq);

    cudaFuncSetAttribute(k10_pixels,
        cudaFuncAttributeMaxDynamicSharedMemorySize, (32768 + 16) * 4);

    // Phase A: tokenizer
    k_pack_kq<<<1024, 256>>>(key_W, key_b, query_W, query_b, p_Wkq, p_bkq);
    k1_proj<<<dim3(4, 256), 128>>>(X, tok_W, p_Tp);
    k2_softmax<<<512, 256>>>(p_Tp, tok_b, p_attn);
    k3_aggregate<<<dim3(2, 16, 32), 128>>>(X, p_attn, p_Tp);
    k3b_reduce<<<512, 256>>>(p_Tp, p_T);

    // Phase B: token transformer (split-K GEMMs + epilogues)
    gemm_sk<<<dim3(8, 8, 8), 128>>>(p_T, p_Wkq, p_Tp, 0);
    gemm_fin<<<512, 256>>>(p_Tp, p_bkq, nullptr, p_kq, 0, nullptr, nullptr);
    k5_attn<<<32, 256>>>(p_kq, p_T, p_Td);
    gemm_sk<<<dim3(8, 8, 8), 128>>>(p_Td, f1_W, p_Tp, 0);
    gemm_fin<<<512, 256>>>(p_Tp, f1_b, nullptr, p_h, 1, nullptr, nullptr);
    gemm_sk<<<dim3(8, 8, 8), 128>>>(p_h, f2_W, p_Tp, 0);
    gemm_fin<<<512, 256>>>(p_Tp, f2_b, p_Td, Tout, 0, nullptr, nullptr);

    // Projector token-side transforms (cb fused into TK epilogue)
    gemm_sk<<<dim3(8, 8, 8), 128>>>(Tout, k_W, p_Tp, 0);
    gemm_fin<<<512, 256>>>(p_Tp, k_b, nullptr, p_TK, 0, q_b, p_cb);
    gemm_sk<<<dim3(8, 8, 8), 128>>>(p_TK, q_W, p_Tp, 1);
    gemm_fin<<<512, 256>>>(p_Tp, nullptr, nullptr, p_U, 0, nullptr, nullptr);

    // Phase C: pixel pass
    k10_pixels<<<512, 256, (32768 + 16) * 4>>>(X, p_U, Tout, p_cb, Xout);

    (void)in_sizes; (void)n_in; (void)out_size;
}